// round 2
// baseline (speedup 1.0000x reference)
#include <cuda_runtime.h>
#include <cuda_bf16.h>
#include <stdint.h>

#define BHN 16
#define LEN 2048
#define DIM 64
#define RN  4
#define NB2 16
#define CH  128
#define NK  256

// ---------------- scratch (device globals; allocation-free) ----------------
__device__ float g_qn  [BHN][LEN][DIM];
__device__ float g_rmn [BHN][DIM][64];
__device__ int   g_hash[BHN][RN][LEN];
__device__ int   g_hidx[BHN][RN][LEN];
__device__ int   g_oidx[BHN][RN][LEN];
__device__ float g_sc  [BHN][RN][LEN][NK];   // scores, then p (in-place)
__device__ float g_attn[BHN][RN][LEN][DIM];  // per-round attn, sorted order

// ---------------- f32x2 helpers ----------------
__device__ __forceinline__ unsigned long long dup2(float v) {
    unsigned long long r;
    asm("mov.b64 %0, {%1, %1};" : "=l"(r) : "r"(__float_as_uint(v)));
    return r;
}
__device__ __forceinline__ unsigned long long fma2(unsigned long long a, unsigned long long b, unsigned long long c) {
    unsigned long long d;
    asm("fma.rn.f32x2 %0, %1, %2, %3;" : "=l"(d) : "l"(a), "l"(b), "l"(c));
    return d;
}
__device__ __forceinline__ float2 unpk2(unsigned long long v) {
    unsigned int lo, hi;
    asm("mov.b64 {%0, %1}, %2;" : "=r"(lo), "=r"(hi) : "l"(v));
    float2 f; f.x = __uint_as_float(lo); f.y = __uint_as_float(hi);
    return f;
}

// fast exp on the FMA pipe (no MUFU). x <= 0. rel err ~3e-6.
__device__ __forceinline__ float fexp(float x) {
    x = fmaxf(x, -87.0f);
    float t = fmaf(x, 1.4426950408889634f, 12582912.0f);
    int n = __float_as_int(t) - 0x4B400000;
    float fi = t - 12582912.0f;
    float z = fmaf(fi, -0.6931471805599453f, x);
    float p = 8.3333337e-3f;
    p = fmaf(p, z, 4.1666668e-2f);
    p = fmaf(p, z, 0.16666667f);
    p = fmaf(p, z, 0.5f);
    p = fmaf(p, z, 1.0f);
    p = fmaf(p, z, 1.0f);
    return p * __int_as_float((n + 127) << 23);
}

// ---------------- K0: normalize rand_matrix columns (over d) ----------------
__global__ void k_rmn(const float* __restrict__ rm) {
    int b = blockIdx.x;
    int j = threadIdx.x; // r*16+k
    float s = 0.f;
    for (int d = 0; d < DIM; d++) {
        float v = rm[(size_t)(b * DIM + d) * 64 + j];
        s += v * v;
    }
    float inv = rsqrtf(s);
    for (int d = 0; d < DIM; d++)
        g_rmn[b][d][j] = rm[(size_t)(b * DIM + d) * 64 + j] * inv;
}

// ---------------- K1: normalize q + hashes ----------------
__global__ void __launch_bounds__(128) k_hash(const float* __restrict__ q) {
    int b = blockIdx.y;
    __shared__ float s_rm[DIM * 64];
    int tid = threadIdx.x;
    const float4* rsrc = (const float4*)&g_rmn[b][0][0];
    for (int t = tid; t < DIM * 64 / 4; t += 128) ((float4*)s_rm)[t] = rsrc[t];
    __syncthreads();

    int l = blockIdx.x * 128 + tid;
    float qv[DIM];
    const float4* qp = (const float4*)&q[((size_t)b * LEN + l) * DIM];
#pragma unroll
    for (int t = 0; t < 16; t++) {
        float4 v = qp[t];
        qv[4 * t] = v.x; qv[4 * t + 1] = v.y; qv[4 * t + 2] = v.z; qv[4 * t + 3] = v.w;
    }
    float ss = 0.f;
#pragma unroll
    for (int d = 0; d < DIM; d++) ss += qv[d] * qv[d];
    float inv = rsqrtf(ss);
#pragma unroll
    for (int d = 0; d < DIM; d++) qv[d] *= inv;
    float4* qd = (float4*)&g_qn[b][l][0];
#pragma unroll
    for (int t = 0; t < 16; t++)
        qd[t] = make_float4(qv[4 * t], qv[4 * t + 1], qv[4 * t + 2], qv[4 * t + 3]);

    for (int r = 0; r < RN; r++) {
        float bp = -1e30f, bn = -1e30f;
        int bpi = 0, bni = 0;
        for (int k = 0; k < 16; k++) {
            float acc = 0.f;
#pragma unroll
            for (int d = 0; d < DIM; d++) acc += qv[d] * s_rm[d * 64 + r * 16 + k];
            if (acc > bp)  { bp = acc;  bpi = k; }
            if (-acc > bn) { bn = -acc; bni = k; }
        }
        g_hash[b][r][l] = (bn > bp) ? (16 + bni) : bpi;
    }
}

// ---------------- K2: stable counting sort per (b,r) ----------------
__global__ void __launch_bounds__(256) k_sort() {
    int b = blockIdx.x >> 2, r = blockIdx.x & 3;
    __shared__ int hist[32][257];
    __shared__ int base[32];
    int t = threadIdx.x;
#pragma unroll
    for (int v = 0; v < 32; v++) hist[v][t] = 0;
    __syncthreads();
    int h[8];
#pragma unroll
    for (int e = 0; e < 8; e++) {
        h[e] = g_hash[b][r][t * 8 + e];
        hist[h[e]][t]++;
    }
    __syncthreads();
    if (t < 32) {
        int run = 0;
        for (int i = 0; i < 256; i++) { int x = hist[t][i]; hist[t][i] = run; run += x; }
        base[t] = run;
    }
    __syncthreads();
    if (t == 0) {
        int run = 0;
        for (int v = 0; v < 32; v++) { int x = base[v]; base[v] = run; run += x; }
    }
    __syncthreads();
#pragma unroll
    for (int e = 0; e < 8; e++) {
        int l = t * 8 + e, v = h[e];
        int off = hist[v][t];
        hist[v][t] = off + 1;
        int pos = base[v] + off;
        g_hidx[b][r][pos] = l;
        g_oidx[b][r][l] = pos;
    }
}

// ---------------- K3: masked score GEMM per (b,r,chunk) ----------------
__global__ void __launch_bounds__(512) k_scores() {
    int n = blockIdx.x, r = blockIdx.y, b = blockIdx.z;
    extern __shared__ float sm3[];
    float* ks  = sm3;                      // [64][256], d-major
    int* kidx  = (int*)(sm3 + DIM * NK);   // [256]
    int* khash = kidx + NK;                // [256]
    int tid = threadIdx.y * 16 + threadIdx.x;
    int prevbase = ((n + NB2 - 1) & (NB2 - 1)) * CH;

    for (int j = tid; j < NK; j += 512) {
        int keypos = (j < CH) ? (prevbase + j) : (n * CH + j - CH);
        int ki = g_hidx[b][r][keypos];
        kidx[j] = ki;
        khash[j] = g_hash[b][r][ki];
    }
    __syncthreads();
    for (int tsk = tid; tsk < NK * 16; tsk += 512) {
        int c = tsk >> 8, j = tsk & 255;
        float4 v = *(const float4*)&g_qn[b][kidx[j]][c * 4];
        ks[(c * 4 + 0) * NK + j] = v.x;
        ks[(c * 4 + 1) * NK + j] = v.y;
        ks[(c * 4 + 2) * NK + j] = v.z;
        ks[(c * 4 + 3) * NK + j] = v.w;
    }
    __syncthreads();

    int ti = threadIdx.x;   // i = ti + 16*e
    int tj = threadIdx.y;   // j = tj*8 + 2f+{0,1}
    int j0 = tj * 8;
    unsigned long long acc[8][4];
#pragma unroll
    for (int e = 0; e < 8; e++)
#pragma unroll
        for (int f = 0; f < 4; f++) acc[e][f] = 0ull;

    for (int d = 0; d < DIM; d++) {
        const float* row = ks + d * NK;
        unsigned long long kv[4];
#pragma unroll
        for (int f = 0; f < 4; f++)
            kv[f] = *(const unsigned long long*)&row[j0 + 2 * f];
#pragma unroll
        for (int e = 0; e < 8; e++) {
            unsigned long long qp = dup2(row[CH + ti + 16 * e]);
#pragma unroll
            for (int f = 0; f < 4; f++) acc[e][f] = fma2(qp, kv[f], acc[e][f]);
        }
    }

#pragma unroll
    for (int e = 0; e < 8; e++) {
        int i = ti + 16 * e;
        int qidx = kidx[CH + i];
        int qh   = khash[CH + i];
        float o[8];
#pragma unroll
        for (int f = 0; f < 4; f++) {
            float2 v = unpk2(acc[e][f]);
            o[2 * f] = v.x; o[2 * f + 1] = v.y;
        }
#pragma unroll
        for (int g = 0; g < 8; g++) {
            int j = j0 + g;
            float s = o[g] * 0.125f;
            int kj = kidx[j];
            if (qidx == kj)                       s = -100000.0f;
            else if (qidx < kj || qh != khash[j]) s = -1000000000.0f;
            o[g] = s;
        }
        float4* dst = (float4*)&g_sc[b][r][n * CH + i][j0];
        dst[0] = make_float4(o[0], o[1], o[2], o[3]);
        dst[1] = make_float4(o[4], o[5], o[6], o[7]);
    }
}

// ---------------- K4: dup-count + joint softmax (in-place) ----------------
__global__ void __launch_bounds__(512) k_softmax() {
    int b = blockIdx.y;
    __shared__ int s_hidx[RN * LEN];
    __shared__ int s_pc[LEN];
    __shared__ float s_log[4];
    int tid = threadIdx.x;
    if (tid == 0) { s_log[0] = 0.0f; s_log[1] = 0.6931471805599453f;
                    s_log[2] = 1.0986122886681098f; s_log[3] = 1.3862943611198906f; }
    for (int t = tid; t < RN * LEN; t += 512) s_hidx[t] = (&g_hidx[b][0][0])[t];
    for (int k = tid; k < LEN; k += 512) {
        int v = 0;
#pragma unroll
        for (int r = 0; r < RN; r++) v |= ((g_oidx[b][r][k] >> 7) & 15) << (8 * r);
        s_pc[k] = v;
    }
    __syncthreads();
    int warp = tid >> 5, lane = tid & 31;
#pragma unroll 1
    for (int it = 0; it < 16; it++) {
        int l = blockIdx.x * 256 + it * 16 + warp;
        int srs[RN];
        int npack = 0, ppack = 0;
#pragma unroll
        for (int r = 0; r < RN; r++) {
            srs[r] = g_oidx[b][r][l];
            int n = srs[r] >> 7;
            npack |= n << (8 * r);
            ppack |= ((n + 15) & 15) << (8 * r);
        }
        float adj[RN][8];
        float mx = -3.4e38f;
#pragma unroll
        for (int r = 0; r < RN; r++) {
            int n = srs[r] >> 7;
            int prevbase = ((n + 15) & 15) << 7;
            const float* srow = &g_sc[b][r][srs[r]][0];
#pragma unroll
            for (int c = 0; c < 8; c++) {
                int j = c * 32 + lane;
                int keypos = (c < 4) ? (prevbase + j) : ((n << 7) + j - CH);
                int k = s_hidx[r * LEN + keypos];
                unsigned m = __vcmpeq4((unsigned)s_pc[k], (unsigned)npack)
                           | __vcmpeq4((unsigned)s_pc[k], (unsigned)ppack);
                int cnt = __popc(m) >> 3;
                float a = srow[j] - s_log[cnt - 1];
                adj[r][c] = a;
                mx = fmaxf(mx, a);
            }
        }
#pragma unroll
        for (int o = 16; o; o >>= 1) mx = fmaxf(mx, __shfl_xor_sync(0xffffffffu, mx, o));
        float sum = 0.f;
#pragma unroll
        for (int r = 0; r < RN; r++)
#pragma unroll
            for (int c = 0; c < 8; c++) {
                float e = fexp(adj[r][c] - mx);
                adj[r][c] = e;
                sum += e;
            }
#pragma unroll
        for (int o = 16; o; o >>= 1) sum += __shfl_xor_sync(0xffffffffu, sum, o);
        float inv = 1.0f / sum;
#pragma unroll
        for (int r = 0; r < RN; r++) {
            float* srow = &g_sc[b][r][srs[r]][0];
#pragma unroll
            for (int c = 0; c < 8; c++) srow[c * 32 + lane] = adj[r][c] * inv;
        }
    }
}

// ---------------- K5: p @ v_sorted per (b,r,chunk) ----------------
__global__ void __launch_bounds__(256) k_av(const float* __restrict__ v) {
    int n = blockIdx.x, r = blockIdx.y, b = blockIdx.z;
    extern __shared__ float s_vs[];  // [256][64]
    int tid = threadIdx.x;
    int prevbase = ((n + NB2 - 1) & (NB2 - 1)) * CH;
    for (int idx = tid; idx < NK * 16; idx += 256) {
        int j = idx >> 4, f = idx & 15;
        int keypos = (j < CH) ? (prevbase + j) : (n * CH + j - CH);
        int ki = g_hidx[b][r][keypos];
        *(float4*)&s_vs[j * 64 + f * 4] = *(const float4*)&v[((size_t)b * LEN + ki) * DIM + f * 4];
    }
    __syncthreads();

    int warp = tid >> 5, lane = tid & 31;
    int i0 = warp * 16;
    unsigned long long acc[16];
#pragma unroll
    for (int i = 0; i < 16; i++) acc[i] = 0ull;
    const float* prow = &g_sc[b][r][n * CH + i0][0];
    for (int jj = 0; jj < NK; jj += 4) {
        unsigned long long v2[4];
#pragma unroll
        for (int t = 0; t < 4; t++)
            v2[t] = *(const unsigned long long*)&s_vs[(jj + t) * 64 + lane * 2];
#pragma unroll
        for (int i = 0; i < 16; i++) {
            float4 p4 = *(const float4*)&prow[i * NK + jj];
            acc[i] = fma2(dup2(p4.x), v2[0], acc[i]);
            acc[i] = fma2(dup2(p4.y), v2[1], acc[i]);
            acc[i] = fma2(dup2(p4.z), v2[2], acc[i]);
            acc[i] = fma2(dup2(p4.w), v2[3], acc[i]);
        }
    }
#pragma unroll
    for (int i = 0; i < 16; i++)
        *(unsigned long long*)&g_attn[b][r][n * CH + i0 + i][lane * 2] = acc[i];
}

// ---------------- K6: gather rounds back to original order, sum ----------------
__global__ void __launch_bounds__(256) k_out(float* __restrict__ out) {
    int gid = blockIdx.x * 256 + threadIdx.x;  // 16*2048*16
    int dq = gid & 15;
    int l = (gid >> 4) & (LEN - 1);
    int b = gid >> 15;
    float4 s = make_float4(0.f, 0.f, 0.f, 0.f);
#pragma unroll
    for (int r = 0; r < RN; r++) {
        int sIdx = g_oidx[b][r][l];
        float4 a = *(const float4*)&g_attn[b][r][sIdx][dq * 4];
        s.x += a.x; s.y += a.y; s.z += a.z; s.w += a.w;
    }
    *(float4*)&out[((size_t)b * LEN + l) * DIM + dq * 4] = s;
}

// ---------------- launch ----------------
extern "C" void kernel_launch(void* const* d_in, const int* in_sizes, int n_in,
                              void* d_out, int out_size) {
    const float* q  = (const float*)d_in[0];
    const float* v  = (const float*)d_in[1];
    const float* rm = (const float*)d_in[2];
    float* out = (float*)d_out;

    const int smem3 = DIM * NK * 4 + NK * 8;  // 67584
    const int smem5 = NK * DIM * 4;           // 65536
    cudaFuncSetAttribute(k_scores, cudaFuncAttributeMaxDynamicSharedMemorySize, smem3);
    cudaFuncSetAttribute(k_av,     cudaFuncAttributeMaxDynamicSharedMemorySize, smem5);

    k_rmn<<<BHN, 64>>>(rm);
    k_hash<<<dim3(LEN / 128, BHN), 128>>>(q);
    k_sort<<<BHN * RN, 256>>>();
    k_scores<<<dim3(NB2, RN, BHN), dim3(16, 32), smem3>>>();
    k_softmax<<<dim3(LEN / 256, BHN), 512>>>();
    k_av<<<dim3(NB2, RN, BHN), 256, smem5>>>(v);
    k_out<<<(BHN * LEN * 16) / 256, 256>>>(out);
}

// round 5
// speedup vs baseline: 1.0174x; 1.0174x over previous
#include <cuda_runtime.h>
#include <cuda_bf16.h>
#include <stdint.h>

#define BHN 16
#define LEN 2048
#define DIM 64
#define RN  4
#define NB2 16
#define CH  128
#define NK  256

typedef unsigned long long ull;

// ---------------- scratch (device globals; allocation-free) ----------------
__device__ float  g_qn  [BHN][LEN][DIM];
__device__ float  g_rmn [BHN][DIM][64];
__device__ int    g_hash[BHN][RN][LEN];
__device__ int    g_hidx[BHN][RN][LEN];
__device__ int    g_oidx[BHN][RN][LEN];
__device__ int    g_pc  [BHN][LEN];          // packed chunk per round
__device__ int    g_ppc [BHN][LEN];          // packed (chunk-1)&15 per round
__device__ float  g_sc  [BHN][RN][LEN][NK];  // adjusted scores, then p (in-place)
__device__ float  g_attn[BHN][RN][LEN][DIM]; // per-round attn, sorted order

__constant__ float c_log4[4] = {0.0f, 0.6931471805599453f, 1.0986122886681098f, 1.3862943611198906f};

// ---------------- f32x2 helpers ----------------
__device__ __forceinline__ ull dup2(float v) {
    ull r;
    asm("mov.b64 %0, {%1, %1};" : "=l"(r) : "r"(__float_as_uint(v)));
    return r;
}
__device__ __forceinline__ ull fma2(ull a, ull b, ull c) {
    ull d;
    asm("fma.rn.f32x2 %0, %1, %2, %3;" : "=l"(d) : "l"(a), "l"(b), "l"(c));
    return d;
}
__device__ __forceinline__ float2 unpk2(ull v) {
    unsigned int lo, hi;
    asm("mov.b64 {%0, %1}, %2;" : "=r"(lo), "=r"(hi) : "l"(v));
    float2 f; f.x = __uint_as_float(lo); f.y = __uint_as_float(hi);
    return f;
}

// fast exp on the FMA pipe — R2's exact version (bit-identical experiment)
__device__ __forceinline__ float fexp(float x) {
    x = fmaxf(x, -87.0f);
    float t = fmaf(x, 1.4426950408889634f, 12582912.0f);
    int n = __float_as_int(t) - 0x4B400000;
    float fi = t - 12582912.0f;
    float z = fmaf(fi, -0.6931471805599453f, x);
    float p = 8.3333337e-3f;
    p = fmaf(p, z, 4.1666668e-2f);
    p = fmaf(p, z, 0.16666667f);
    p = fmaf(p, z, 0.5f);
    p = fmaf(p, z, 1.0f);
    p = fmaf(p, z, 1.0f);
    return p * __int_as_float((n + 127) << 23);
}

// ---------------- K0: normalize rand_matrix columns ----------------
__global__ void k_rmn(const float* __restrict__ rm) {
    int b = blockIdx.x;
    int j = threadIdx.x;
    float s = 0.f;
    for (int d = 0; d < DIM; d++) {
        float v = rm[(size_t)(b * DIM + d) * 64 + j];
        s += v * v;
    }
    float inv = rsqrtf(s);
    for (int d = 0; d < DIM; d++)
        g_rmn[b][d][j] = rm[(size_t)(b * DIM + d) * 64 + j] * inv;
}

// ---------------- K1: normalize q + hashes ----------------
__global__ void __launch_bounds__(128) k_hash(const float* __restrict__ q) {
    int b = blockIdx.y;
    __shared__ float s_rm[DIM * 64];
    int tid = threadIdx.x;
    const float4* rsrc = (const float4*)&g_rmn[b][0][0];
    for (int t = tid; t < DIM * 64 / 4; t += 128) ((float4*)s_rm)[t] = rsrc[t];
    __syncthreads();

    int l = blockIdx.x * 128 + tid;
    float qv[DIM];
    const float4* qp = (const float4*)&q[((size_t)b * LEN + l) * DIM];
#pragma unroll
    for (int t = 0; t < 16; t++) {
        float4 v = qp[t];
        qv[4 * t] = v.x; qv[4 * t + 1] = v.y; qv[4 * t + 2] = v.z; qv[4 * t + 3] = v.w;
    }
    float ss = 0.f;
#pragma unroll
    for (int d = 0; d < DIM; d++) ss += qv[d] * qv[d];
    float inv = rsqrtf(ss);
#pragma unroll
    for (int d = 0; d < DIM; d++) qv[d] *= inv;
    float4* qd = (float4*)&g_qn[b][l][0];
#pragma unroll
    for (int t = 0; t < 16; t++)
        qd[t] = make_float4(qv[4 * t], qv[4 * t + 1], qv[4 * t + 2], qv[4 * t + 3]);

    for (int r = 0; r < RN; r++) {
        float bp = -1e30f, bn = -1e30f;
        int bpi = 0, bni = 0;
        for (int k = 0; k < 16; k++) {
            float acc = 0.f;
#pragma unroll
            for (int d = 0; d < DIM; d++) acc += qv[d] * s_rm[d * 64 + r * 16 + k];
            if (acc > bp)  { bp = acc;  bpi = k; }
            if (-acc > bn) { bn = -acc; bni = k; }
        }
        g_hash[b][r][l] = (bn > bp) ? (16 + bni) : bpi;
    }
}

// ---------------- K2: stable counting sort per (b,r) ----------------
__global__ void __launch_bounds__(256) k_sort() {
    int b = blockIdx.x >> 2, r = blockIdx.x & 3;
    __shared__ int hist[32][257];
    __shared__ int base[32];
    int t = threadIdx.x;
#pragma unroll
    for (int v = 0; v < 32; v++) hist[v][t] = 0;
    __syncthreads();
    int h[8];
#pragma unroll
    for (int e = 0; e < 8; e++) {
        h[e] = g_hash[b][r][t * 8 + e];
        hist[h[e]][t]++;
    }
    __syncthreads();
    if (t < 32) {
        int run = 0;
        for (int i = 0; i < 256; i++) { int x = hist[t][i]; hist[t][i] = run; run += x; }
        base[t] = run;
    }
    __syncthreads();
    if (t == 0) {
        int run = 0;
        for (int v = 0; v < 32; v++) { int x = base[v]; base[v] = run; run += x; }
    }
    __syncthreads();
#pragma unroll
    for (int e = 0; e < 8; e++) {
        int l = t * 8 + e, v = h[e];
        int off = hist[v][t];
        hist[v][t] = off + 1;
        int pos = base[v] + off;
        g_hidx[b][r][pos] = l;
        g_oidx[b][r][l] = pos;
    }
}

// ---------------- K2.5: pack per-token chunk ids (cur + prev) ----------------
__global__ void __launch_bounds__(256) k_pack() {
    int gid = blockIdx.x * 256 + threadIdx.x;
    int l = gid & (LEN - 1);
    int b = gid >> 11;
    int v = 0, w = 0;
#pragma unroll
    for (int r = 0; r < RN; r++) {
        int n = (g_oidx[b][r][l] >> 7) & 15;
        v |= n << (8 * r);
        w |= ((n + 15) & 15) << (8 * r);
    }
    g_pc[b][l] = v;
    g_ppc[b][l] = w;
}

// ---------------- K3: masked score GEMM + fused count adjust ----------------
__device__ __forceinline__ void ld_dk(const float* ks, int j0, int ti, int d,
                                      ull kv[4], float qv[8]) {
    const float* rw = ks + d * NK;
    ulonglong2 t0 = *(const ulonglong2*)(rw + j0);
    ulonglong2 t1 = *(const ulonglong2*)(rw + j0 + 4);
    kv[0] = t0.x; kv[1] = t0.y; kv[2] = t1.x; kv[3] = t1.y;
#pragma unroll
    for (int e = 0; e < 8; e++) qv[e] = rw[CH + ti + 16 * e];
}
__device__ __forceinline__ void fma_dk(ull acc[8][4], const ull kv[4], const float qv[8]) {
#pragma unroll
    for (int e = 0; e < 8; e++) {
        ull qp = dup2(qv[e]);
#pragma unroll
        for (int f = 0; f < 4; f++) acc[e][f] = fma2(qp, kv[f], acc[e][f]);
    }
}

__global__ void __launch_bounds__(512) k_scores() {
    int n = blockIdx.x, r = blockIdx.y, b = blockIdx.z;
    extern __shared__ float sm3[];
    float* ks    = sm3;                        // [64][256]
    int*   kidx  = (int*)(sm3 + DIM * NK);     // [256]
    int*   khash = kidx + NK;                  // [256]
    int*   kpc   = khash + NK;                 // [256]
    int*   kppc  = kpc + NK;                   // [256]
    int tid = threadIdx.y * 16 + threadIdx.x;
    int prevbase = ((n + NB2 - 1) & (NB2 - 1)) * CH;

    for (int j = tid; j < NK; j += 512) {
        int keypos = (j < CH) ? (prevbase + j) : (n * CH + j - CH);
        int ki = g_hidx[b][r][keypos];
        kidx[j] = ki;
        khash[j] = g_hash[b][r][ki];
        kpc[j]  = g_pc[b][ki];
        kppc[j] = g_ppc[b][ki];
    }
    __syncthreads();
    for (int tsk = tid; tsk < NK * 16; tsk += 512) {
        int c = tsk >> 8, j = tsk & 255;
        float4 v = *(const float4*)&g_qn[b][kidx[j]][c * 4];
        ks[(c * 4 + 0) * NK + j] = v.x;
        ks[(c * 4 + 1) * NK + j] = v.y;
        ks[(c * 4 + 2) * NK + j] = v.z;
        ks[(c * 4 + 3) * NK + j] = v.w;
    }
    __syncthreads();

    int ti = threadIdx.x;
    int tj = threadIdx.y;
    int j0 = tj * 8;
    ull acc[8][4];
#pragma unroll
    for (int e = 0; e < 8; e++)
#pragma unroll
        for (int f = 0; f < 4; f++) acc[e][f] = 0ull;

    ull kvA[4], kvB[4];
    float qA[8], qB[8];
    ld_dk(ks, j0, ti, 0, kvA, qA);
#pragma unroll 2
    for (int d = 0; d < DIM; d += 2) {
        ld_dk(ks, j0, ti, d + 1, kvB, qB);
        fma_dk(acc, kvA, qA);
        ld_dk(ks, j0, ti, (d + 2) & 63, kvA, qA);
        fma_dk(acc, kvB, qB);
    }

#pragma unroll
    for (int e = 0; e < 8; e++) {
        int i = ti + 16 * e;
        int qidx = kidx[CH + i];
        int qh   = khash[CH + i];
        int np   = kpc[CH + i];
        int pp   = kppc[CH + i];
        float o[8];
#pragma unroll
        for (int f = 0; f < 4; f++) {
            float2 v = unpk2(acc[e][f]);
            o[2 * f] = v.x; o[2 * f + 1] = v.y;
        }
#pragma unroll
        for (int g = 0; g < 8; g++) {
            int j = j0 + g;
            float s = o[g] * 0.125f;
            int kj = kidx[j];
            if (qidx == kj)                       s = -100000.0f;
            else if (qidx < kj || qh != khash[j]) s = -1000000000.0f;
            unsigned m = __vcmpeq4((unsigned)kpc[j], (unsigned)np)
                       | __vcmpeq4((unsigned)kpc[j], (unsigned)pp);
            s -= c_log4[(__popc(m) >> 3) - 1];
            o[g] = s;
        }
        float4* dst = (float4*)&g_sc[b][r][n * CH + i][j0];
        dst[0] = make_float4(o[0], o[1], o[2], o[3]);
        dst[1] = make_float4(o[4], o[5], o[6], o[7]);
    }
}

// ---------------- K4: joint softmax over pre-adjusted scores (in-place, R2 path) ----------------
__global__ void __launch_bounds__(512) k_softmax() {
    int b = blockIdx.y;
    int warp = threadIdx.x >> 5, lane = threadIdx.x & 31;
#pragma unroll 1
    for (int it = 0; it < 16; it++) {
        int l = blockIdx.x * 256 + it * 16 + warp;
        int srs[RN];
        float adj[RN][8];
        float mx = -3.4e38f;
#pragma unroll
        for (int r = 0; r < RN; r++) {
            srs[r] = g_oidx[b][r][l];
            const float* srow = &g_sc[b][r][srs[r]][0];
#pragma unroll
            for (int c = 0; c < 8; c++) {
                float a = srow[c * 32 + lane];
                adj[r][c] = a;
                mx = fmaxf(mx, a);
            }
        }
#pragma unroll
        for (int o = 16; o; o >>= 1) mx = fmaxf(mx, __shfl_xor_sync(0xffffffffu, mx, o));
        float sum = 0.f;
#pragma unroll
        for (int r = 0; r < RN; r++)
#pragma unroll
            for (int c = 0; c < 8; c++) {
                float e = fexp(adj[r][c] - mx);
                adj[r][c] = e;
                sum += e;
            }
#pragma unroll
        for (int o = 16; o; o >>= 1) sum += __shfl_xor_sync(0xffffffffu, sum, o);
        float inv = 1.0f / sum;
#pragma unroll
        for (int r = 0; r < RN; r++) {
            float* srow = &g_sc[b][r][srs[r]][0];
#pragma unroll
            for (int c = 0; c < 8; c++) srow[c * 32 + lane] = adj[r][c] * inv;
        }
    }
}

// ---------------- K5: p @ v_sorted per (b,r,chunk) — R2 verbatim ----------------
__global__ void __launch_bounds__(256) k_av(const float* __restrict__ v) {
    int n = blockIdx.x, r = blockIdx.y, b = blockIdx.z;
    extern __shared__ float s_vs[];  // [256][64]
    int tid = threadIdx.x;
    int prevbase = ((n + NB2 - 1) & (NB2 - 1)) * CH;
    for (int idx = tid; idx < NK * 16; idx += 256) {
        int j = idx >> 4, f = idx & 15;
        int keypos = (j < CH) ? (prevbase + j) : (n * CH + j - CH);
        int ki = g_hidx[b][r][keypos];
        *(float4*)&s_vs[j * 64 + f * 4] = *(const float4*)&v[((size_t)b * LEN + ki) * DIM + f * 4];
    }
    __syncthreads();

    int warp = tid >> 5, lane = tid & 31;
    int i0 = warp * 16;
    ull acc[16];
#pragma unroll
    for (int i = 0; i < 16; i++) acc[i] = 0ull;
    const float* prow = &g_sc[b][r][n * CH + i0][0];
    for (int jj = 0; jj < NK; jj += 4) {
        ull v2[4];
#pragma unroll
        for (int t = 0; t < 4; t++)
            v2[t] = *(const ull*)&s_vs[(jj + t) * 64 + lane * 2];
#pragma unroll
        for (int i = 0; i < 16; i++) {
            float4 p4 = *(const float4*)&prow[i * NK + jj];
            acc[i] = fma2(dup2(p4.x), v2[0], acc[i]);
            acc[i] = fma2(dup2(p4.y), v2[1], acc[i]);
            acc[i] = fma2(dup2(p4.z), v2[2], acc[i]);
            acc[i] = fma2(dup2(p4.w), v2[3], acc[i]);
        }
    }
#pragma unroll
    for (int i = 0; i < 16; i++)
        *(ull*)&g_attn[b][r][n * CH + i0 + i][lane * 2] = acc[i];
}

// ---------------- K6: gather rounds back to original order, sum ----------------
__global__ void __launch_bounds__(256) k_out(float* __restrict__ out) {
    int gid = blockIdx.x * 256 + threadIdx.x;
    int dq = gid & 15;
    int l = (gid >> 4) & (LEN - 1);
    int b = gid >> 15;
    float4 s = make_float4(0.f, 0.f, 0.f, 0.f);
#pragma unroll
    for (int r = 0; r < RN; r++) {
        int sIdx = g_oidx[b][r][l];
        float4 a = *(const float4*)&g_attn[b][r][sIdx][dq * 4];
        s.x += a.x; s.y += a.y; s.z += a.z; s.w += a.w;
    }
    *(float4*)&out[((size_t)b * LEN + l) * DIM + dq * 4] = s;
}

// ---------------- launch ----------------
extern "C" void kernel_launch(void* const* d_in, const int* in_sizes, int n_in,
                              void* d_out, int out_size) {
    const float* q  = (const float*)d_in[0];
    const float* v  = (const float*)d_in[1];
    const float* rm = (const float*)d_in[2];
    float* out = (float*)d_out;

    const int smem3 = DIM * NK * 4 + 4 * NK * 4;  // 69632
    const int smem5 = NK * DIM * 4;               // 65536
    cudaFuncSetAttribute(k_scores, cudaFuncAttributeMaxDynamicSharedMemorySize, smem3);
    cudaFuncSetAttribute(k_av,     cudaFuncAttributeMaxDynamicSharedMemorySize, smem5);

    k_rmn<<<BHN, 64>>>(rm);
    k_hash<<<dim3(LEN / 128, BHN), 128>>>(q);
    k_sort<<<BHN * RN, 256>>>();
    k_pack<<<BHN * LEN / 256, 256>>>();
    k_scores<<<dim3(NB2, RN, BHN), dim3(16, 32), smem3>>>();
    k_softmax<<<dim3(LEN / 256, BHN), 512>>>();
    k_av<<<dim3(NB2, RN, BHN), 256, smem5>>>(v);
    k_out<<<(BHN * LEN * 16) / 256, 256>>>(out);
}